// round 1
// baseline (speedup 1.0000x reference)
#include <cuda_runtime.h>
#include <math.h>

#define N_NODES 50000
#define E_EDGES 800000
#define G_GRAPHS 512
#define HID 64
#define DOUT 128
#define LAYERS 3
#define DE 16
#define NEG_SLOPE 0.2f
#define BN_EPS 1e-5f

// ---------------- scratch (device globals; no allocation allowed) ----------------
__device__ float g_h  [N_NODES * HID];
__device__ float g_xl [N_NODES * HID];
__device__ float g_xr [N_NODES * HID];
__device__ float g_acc[N_NODES * HID];
__device__ float g_denom[N_NODES];
__device__ unsigned g_amax[N_NODES];
__device__ float g_logit[E_EDGES];
__device__ float g_cnt[G_GRAPHS];

// monotonic float<->uint encoding for atomicMax on floats
__device__ __forceinline__ unsigned encf(float f) {
    unsigned u = __float_as_uint(f);
    return u ^ (((unsigned)((int)u >> 31)) | 0x80000000u);
}
__device__ __forceinline__ float decf(unsigned u) {
    unsigned b = (u & 0x80000000u) ? (u ^ 0x80000000u) : ~u;
    return __uint_as_float(b);
}
#define ENC_NEG_INF 0x007FFFFFu  // encf(-inf)

__device__ __forceinline__ void redAddF4(float* p, float a, float b, float c, float d) {
    asm volatile("red.global.add.v4.f32 [%0], {%1, %2, %3, %4};"
                 :: "l"(p), "f"(a), "f"(b), "f"(c), "f"(d) : "memory");
}

// ---------------- GEMM: out[n][c] = sum_k A[n][k]*W[c][k] + b[c], K=C=64 ----------------
// srcSel: 0 = use param A, 1 = g_h.  dstSel: 0 = g_h, 1 = g_xl, 2 = g_xr.
__global__ void gemm64(const float* __restrict__ A, const float* __restrict__ W,
                       const float* __restrict__ bias, int srcSel, int dstSel, int n) {
    __shared__ float Ws[64][68];
    __shared__ float As[64][68];
    const float* Ap = srcSel ? g_h : A;
    float* out = (dstSel == 0) ? g_h : (dstSel == 1 ? g_xl : g_xr);

    int t = threadIdx.x;           // 256 threads
    int row0 = blockIdx.x * 64;

    #pragma unroll
    for (int i = t; i < 4096; i += 256) { int c = i >> 6, k = i & 63; Ws[c][k] = W[i]; }
    #pragma unroll
    for (int i = t; i < 4096; i += 256) {
        int r = i >> 6, k = i & 63; int gr = row0 + r;
        As[r][k] = (gr < n) ? Ap[gr * 64 + k] : 0.f;
    }
    __syncthreads();

    int c  = t & 63;
    int rb = t >> 6;               // 0..3, rows rb*16 .. rb*16+15
    float acc[16];
    #pragma unroll
    for (int r = 0; r < 16; r++) acc[r] = 0.f;

    #pragma unroll
    for (int k4 = 0; k4 < 16; k4++) {
        float4 w4 = *(const float4*)&Ws[c][k4 * 4];
        #pragma unroll
        for (int r = 0; r < 16; r++) {
            float4 a4 = *(const float4*)&As[rb * 16 + r][k4 * 4];
            acc[r] += w4.x * a4.x + w4.y * a4.y + w4.z * a4.z + w4.w * a4.w;
        }
    }
    float bb = bias[c];
    #pragma unroll
    for (int r = 0; r < 16; r++) {
        int gr = row0 + rb * 16 + r;
        if (gr < n) out[gr * 64 + c] = acc[r] + bb;
    }
}

// ---------------- per-layer init ----------------
__global__ void init_layer() {
    int idx = blockIdx.x * blockDim.x + threadIdx.x;
    if (idx < N_NODES * HID) g_acc[idx] = 0.f;
    if (idx < N_NODES) { g_denom[idx] = 0.f; g_amax[idx] = ENC_NEG_INF; }
}

// ---------------- edge pass 1: attention logits + segment max ----------------
// one warp per edge; lane handles channels (lane, lane+32)
__global__ void edge_logits(const int* __restrict__ ei, const float* __restrict__ eattr,
                            const float* __restrict__ We, const float* __restrict__ att) {
    __shared__ float sWeT[16 * 64];   // sWeT[k*64+c] = We[c*16+k]
    __shared__ float satt[64];
    int t = threadIdx.x;
    for (int i = t; i < 1024; i += 256) {
        int c = i >> 4, k = i & 15;
        sWeT[k * 64 + c] = We[i];
    }
    if (t < 64) satt[t] = att[t];
    __syncthreads();

    int e = (blockIdx.x * blockDim.x + t) >> 5;
    if (e >= E_EDGES) return;
    int lane = t & 31;

    int src = ei[e];
    int dst = ei[E_EDGES + e];

    float m0 = g_xl[src * 64 + lane]      + g_xr[dst * 64 + lane];
    float m1 = g_xl[src * 64 + lane + 32] + g_xr[dst * 64 + lane + 32];

    const float* eat = eattr + (size_t)e * 16;
    float e0 = 0.f, e1 = 0.f;
    #pragma unroll
    for (int k = 0; k < 16; k++) {
        float a = __ldg(&eat[k]);                // broadcast across warp
        e0 += sWeT[k * 64 + lane]      * a;
        e1 += sWeT[k * 64 + lane + 32] * a;
    }
    m0 += e0; m1 += e1;
    m0 = (m0 > 0.f) ? m0 : NEG_SLOPE * m0;
    m1 = (m1 > 0.f) ? m1 : NEG_SLOPE * m1;

    float p = m0 * satt[lane] + m1 * satt[lane + 32];
    #pragma unroll
    for (int o = 16; o; o >>= 1) p += __shfl_xor_sync(0xffffffffu, p, o);

    if (lane == 0) {
        g_logit[e] = p;
        atomicMax(&g_amax[dst], encf(p));
    }
}

// ---------------- edge pass 2: exp-weight + scatter numerator/denominator ----------------
// 16 threads per edge; thread q handles channels 4q..4q+3
__global__ void edge_scatter(const int* __restrict__ ei) {
    long long gid = (long long)blockIdx.x * blockDim.x + threadIdx.x;
    int e = (int)(gid >> 4);
    if (e >= E_EDGES) return;
    int q = (int)(gid & 15);

    int src = ei[e];
    int dst = ei[E_EDGES + e];

    float w = expf(g_logit[e] - decf(g_amax[dst]));
    if (q == 0) atomicAdd(&g_denom[dst], w);

    float4 xv = *(const float4*)&g_xl[src * 64 + q * 4];
    redAddF4(&g_acc[dst * 64 + q * 4], w * xv.x, w * xv.y, w * xv.z, w * xv.w);
}

// ---------------- node update: normalize, bias, BN, gelu, residual ----------------
__global__ void node_update(const float* __restrict__ conv_bias, const float* __restrict__ gamma,
                            const float* __restrict__ beta, const float* __restrict__ mean,
                            const float* __restrict__ var) {
    int idx = blockIdx.x * blockDim.x + threadIdx.x;
    if (idx >= N_NODES * HID) return;
    int c = idx & 63;
    int n = idx >> 6;
    float o = g_acc[idx] / (g_denom[n] + 1e-16f) + conv_bias[c];
    o = (o - mean[c]) * rsqrtf(var[c] + BN_EPS) * gamma[c] + beta[c];
    o = 0.5f * o * (1.f + erff(o * 0.70710678118654752f));   // exact gelu
    g_h[idx] += o;
}

// ---------------- pooling ----------------
__global__ void init_pool(float* __restrict__ out) {
    int idx = blockIdx.x * blockDim.x + threadIdx.x;
    if (idx < G_GRAPHS * DOUT) out[idx] = 0.f;
    if (idx < G_GRAPHS) g_cnt[idx] = 0.f;
}

__global__ void count_nodes(const int* __restrict__ batch) {
    int n = blockIdx.x * blockDim.x + threadIdx.x;
    if (n < N_NODES) atomicAdd(&g_cnt[batch[n]], 1.f);
}

// lin projection fused with pooled sum: pooled[batch[n]][j] += h[n] . lin_W[j] + lin_b[j]
__global__ void lin_pool(const float* __restrict__ W, const float* __restrict__ bias,
                         const int* __restrict__ batch, float* __restrict__ pooled) {
    __shared__ float Ws[128][68];   // Ws[j][k]
    __shared__ float As[32][68];
    int t = threadIdx.x;            // 256
    int row0 = blockIdx.x * 32;

    for (int i = t; i < 128 * 64; i += 256) { int c = i >> 6, k = i & 63; Ws[c][k] = W[i]; }
    for (int i = t; i < 32 * 64; i += 256) {
        int r = i >> 6, k = i & 63; int gr = row0 + r;
        As[r][k] = (gr < N_NODES) ? g_h[gr * 64 + k] : 0.f;
    }
    __syncthreads();

    int c  = t & 127;
    int rb = t >> 7;                // 0..1, 16 rows each
    float acc[16];
    #pragma unroll
    for (int r = 0; r < 16; r++) acc[r] = 0.f;

    #pragma unroll
    for (int k4 = 0; k4 < 16; k4++) {
        float4 w4 = *(const float4*)&Ws[c][k4 * 4];
        #pragma unroll
        for (int r = 0; r < 16; r++) {
            float4 a4 = *(const float4*)&As[rb * 16 + r][k4 * 4];
            acc[r] += w4.x * a4.x + w4.y * a4.y + w4.z * a4.z + w4.w * a4.w;
        }
    }
    float bb = bias[c];
    #pragma unroll
    for (int r = 0; r < 16; r++) {
        int gr = row0 + rb * 16 + r;
        if (gr < N_NODES)
            atomicAdd(&pooled[batch[gr] * DOUT + c], acc[r] + bb);
    }
}

__global__ void finalize(float* __restrict__ out) {
    int idx = blockIdx.x * blockDim.x + threadIdx.x;
    if (idx >= G_GRAPHS * DOUT) return;
    out[idx] /= fmaxf(g_cnt[idx >> 7], 1.f);
}

// ---------------- launch ----------------
extern "C" void kernel_launch(void* const* d_in, const int* in_sizes, int n_in,
                              void* d_out, int out_size) {
    const float* x         = (const float*)d_in[0];
    const int*   ei        = (const int*)  d_in[1];
    const float* eattr     = (const float*)d_in[2];
    const int*   batch     = (const int*)  d_in[3];
    const float* emb_W     = (const float*)d_in[4];
    const float* emb_b     = (const float*)d_in[5];
    const float* Wl        = (const float*)d_in[6];
    const float* bl        = (const float*)d_in[7];
    const float* Wr        = (const float*)d_in[8];
    const float* br        = (const float*)d_in[9];
    const float* We        = (const float*)d_in[10];
    const float* att       = (const float*)d_in[11];
    const float* conv_bias = (const float*)d_in[12];
    const float* gamma     = (const float*)d_in[13];
    const float* beta      = (const float*)d_in[14];
    const float* mean      = (const float*)d_in[15];
    const float* var       = (const float*)d_in[16];
    const float* lin_W     = (const float*)d_in[17];
    const float* lin_b     = (const float*)d_in[18];
    float* out = (float*)d_out;

    const int GEMM_BLOCKS  = (N_NODES + 63) / 64;           // 782
    const int NODE_BLOCKS  = (N_NODES * HID + 255) / 256;   // 12500
    const int EDGE1_BLOCKS = (E_EDGES + 7) / 8;             // 100000 (8 warps/block)
    const int EDGE2_BLOCKS = (E_EDGES * 16 + 255) / 256;    // 50000

    // embedding
    gemm64<<<GEMM_BLOCKS, 256>>>(x, emb_W, emb_b, /*src*/0, /*dst g_h*/0, N_NODES);

    for (int l = 0; l < LAYERS; l++) {
        init_layer<<<NODE_BLOCKS, 256>>>();
        gemm64<<<GEMM_BLOCKS, 256>>>(nullptr, Wl + l * 4096, bl + l * 64, 1, 1, N_NODES); // xl
        gemm64<<<GEMM_BLOCKS, 256>>>(nullptr, Wr + l * 4096, br + l * 64, 1, 2, N_NODES); // xr
        edge_logits<<<EDGE1_BLOCKS, 256>>>(ei, eattr, We + l * 1024, att + l * 64);
        edge_scatter<<<EDGE2_BLOCKS, 256>>>(ei);
        node_update<<<NODE_BLOCKS, 256>>>(conv_bias + l * 64, gamma + l * 64, beta + l * 64,
                                          mean + l * 64, var + l * 64);
    }

    init_pool<<<(G_GRAPHS * DOUT + 255) / 256, 256>>>(out);
    count_nodes<<<(N_NODES + 255) / 256, 256>>>(batch);
    lin_pool<<<(N_NODES + 31) / 32, 256>>>(lin_W, lin_b, batch, out);
    finalize<<<(G_GRAPHS * DOUT + 255) / 256, 256>>>(out);
}

// round 2
// speedup vs baseline: 1.0844x; 1.0844x over previous
#include <cuda_runtime.h>
#include <math.h>

#define N_NODES 50000
#define E_EDGES 800000
#define G_GRAPHS 512
#define HID 64
#define DOUT 128
#define LAYERS 3
#define DE 16
#define NEG_SLOPE 0.2f
#define BN_EPS 1e-5f

// ---------------- scratch (device globals; no allocation allowed) ----------------
__device__ float g_h  [N_NODES * HID];
__device__ float g_xl [N_NODES * HID];
__device__ float g_xr [N_NODES * HID];
__device__ float g_acc[N_NODES * HID];
__device__ float g_denom[N_NODES];
__device__ float g_cnt[G_GRAPHS];

__device__ __forceinline__ void redAddF4(float* p, float a, float b, float c, float d) {
    asm volatile("red.global.add.v4.f32 [%0], {%1, %2, %3, %4};"
                 :: "l"(p), "f"(a), "f"(b), "f"(c), "f"(d) : "memory");
}
__device__ __forceinline__ void redAddF1(float* p, float a) {
    asm volatile("red.global.add.f32 [%0], %1;" :: "l"(p), "f"(a) : "memory");
}

// ---------------- GEMM: out[n][c] = sum_k A[n][k]*W[c][k] + b[c], K=C=64 ----------------
// srcSel: 0 = use param A, 1 = g_h.  dstSel: 0 = g_h, 1 = g_xl, 2 = g_xr.
__global__ void gemm64(const float* __restrict__ A, const float* __restrict__ W,
                       const float* __restrict__ bias, int srcSel, int dstSel, int n) {
    __shared__ float Ws[64][68];
    __shared__ float As[64][68];
    const float* Ap = srcSel ? g_h : A;
    float* out = (dstSel == 0) ? g_h : (dstSel == 1 ? g_xl : g_xr);

    int t = threadIdx.x;           // 256 threads
    int row0 = blockIdx.x * 64;

    #pragma unroll
    for (int i = t; i < 4096; i += 256) { int c = i >> 6, k = i & 63; Ws[c][k] = W[i]; }
    #pragma unroll
    for (int i = t; i < 4096; i += 256) {
        int r = i >> 6, k = i & 63; int gr = row0 + r;
        As[r][k] = (gr < n) ? Ap[gr * 64 + k] : 0.f;
    }
    __syncthreads();

    int c  = t & 63;
    int rb = t >> 6;               // 0..3, rows rb*16 .. rb*16+15
    float acc[16];
    #pragma unroll
    for (int r = 0; r < 16; r++) acc[r] = 0.f;

    #pragma unroll
    for (int k4 = 0; k4 < 16; k4++) {
        float4 w4 = *(const float4*)&Ws[c][k4 * 4];
        #pragma unroll
        for (int r = 0; r < 16; r++) {
            float4 a4 = *(const float4*)&As[rb * 16 + r][k4 * 4];
            acc[r] += w4.x * a4.x + w4.y * a4.y + w4.z * a4.z + w4.w * a4.w;
        }
    }
    float bb = bias[c];
    #pragma unroll
    for (int r = 0; r < 16; r++) {
        int gr = row0 + rb * 16 + r;
        if (gr < n) out[gr * 64 + c] = acc[r] + bb;
    }
}

// ---------------- one-time init of accumulators ----------------
__global__ void init_acc() {
    int idx = blockIdx.x * blockDim.x + threadIdx.x;
    if (idx < N_NODES * HID) g_acc[idx] = 0.f;
    if (idx < N_NODES) g_denom[idx] = 0.f;
}

// ---------------- fused edge pass: logits + exp + scatter (no segment-max) ------
// one warp per edge; lane handles channels (2*lane, 2*lane+1)
__global__ void edge_pass(const int* __restrict__ ei, const float* __restrict__ eattr,
                          const float* __restrict__ We, const float* __restrict__ att) {
    __shared__ float sWeT[16 * 64];   // sWeT[k*64+c] = We[c*16+k]
    __shared__ float satt[64];
    int t = threadIdx.x;
    for (int i = t; i < 1024; i += 256) {
        int c = i >> 4, k = i & 15;
        sWeT[k * 64 + c] = We[i];
    }
    if (t < 64) satt[t] = att[t];
    __syncthreads();

    int e = (blockIdx.x * blockDim.x + t) >> 5;
    if (e >= E_EDGES) return;
    int lane = t & 31;
    int c0 = lane * 2;

    int src = ei[e];
    int dst = ei[E_EDGES + e];

    float2 vl = *(const float2*)&g_xl[src * 64 + c0];
    float2 vr = *(const float2*)&g_xr[dst * 64 + c0];

    // edge_attr @ We.T : lanes 0..3 hold the 16 attrs in float4s, broadcast by shfl
    float4 va = make_float4(0.f, 0.f, 0.f, 0.f);
    if (lane < 4) va = *(const float4*)&eattr[(size_t)e * 16 + lane * 4];

    float m0 = vl.x + vr.x;
    float m1 = vl.y + vr.y;
    #pragma unroll
    for (int k = 0; k < 16; k++) {
        float comp = ((k & 3) == 0) ? va.x : ((k & 3) == 1) ? va.y : ((k & 3) == 2) ? va.z : va.w;
        float a = __shfl_sync(0xffffffffu, comp, k >> 2);
        m0 += sWeT[k * 64 + c0]     * a;
        m1 += sWeT[k * 64 + c0 + 1] * a;
    }
    m0 = (m0 > 0.f) ? m0 : NEG_SLOPE * m0;
    m1 = (m1 > 0.f) ? m1 : NEG_SLOPE * m1;

    float p = m0 * satt[c0] + m1 * satt[c0 + 1];
    #pragma unroll
    for (int o = 16; o; o >>= 1) p += __shfl_xor_sync(0xffffffffu, p, o);

    float w = expf(p);              // |p| is small (weights scaled 0.1) -> safe, no max needed

    if (lane == 0) redAddF1(&g_denom[dst], w);

    // pair lanes so even lanes issue one red.v4 covering 4 consecutive channels
    float s0 = __shfl_down_sync(0xffffffffu, vl.x, 1);
    float s1 = __shfl_down_sync(0xffffffffu, vl.y, 1);
    if ((lane & 1) == 0)
        redAddF4(&g_acc[dst * 64 + c0], w * vl.x, w * vl.y, w * s0, w * s1);
}

// ---------------- node update: normalize, bias, BN, gelu, residual + reset acc ----
__global__ void node_update(const float* __restrict__ conv_bias, const float* __restrict__ gamma,
                            const float* __restrict__ beta, const float* __restrict__ mean,
                            const float* __restrict__ var) {
    int idx = blockIdx.x * blockDim.x + threadIdx.x;
    if (idx >= N_NODES * HID) return;
    int c = idx & 63;
    int n = idx >> 6;
    float acc = g_acc[idx];
    float den = g_denom[n];
    __syncthreads();                     // all reads of g_denom[n] before any reset
    g_acc[idx] = 0.f;                    // reset for next layer
    if (c == 0) g_denom[n] = 0.f;
    float o = acc / (den + 1e-16f) + conv_bias[c];
    o = (o - mean[c]) * rsqrtf(var[c] + BN_EPS) * gamma[c] + beta[c];
    o = 0.5f * o * (1.f + erff(o * 0.70710678118654752f));   // exact gelu
    g_h[idx] += o;
}

// ---------------- pooling ----------------
__global__ void init_pool(float* __restrict__ out) {
    int idx = blockIdx.x * blockDim.x + threadIdx.x;
    if (idx < G_GRAPHS * DOUT) out[idx] = 0.f;
    if (idx < G_GRAPHS) g_cnt[idx] = 0.f;
}

__global__ void count_nodes(const int* __restrict__ batch) {
    int n = blockIdx.x * blockDim.x + threadIdx.x;
    if (n < N_NODES) atomicAdd(&g_cnt[batch[n]], 1.f);
}

// lin projection fused with pooled sum: pooled[batch[n]][j] += h[n] . lin_W[j] + lin_b[j]
__global__ void lin_pool(const float* __restrict__ W, const float* __restrict__ bias,
                         const int* __restrict__ batch, float* __restrict__ pooled) {
    __shared__ float Ws[128][68];   // Ws[j][k]
    __shared__ float As[32][68];
    int t = threadIdx.x;            // 256
    int row0 = blockIdx.x * 32;

    for (int i = t; i < 128 * 64; i += 256) { int c = i >> 6, k = i & 63; Ws[c][k] = W[i]; }
    for (int i = t; i < 32 * 64; i += 256) {
        int r = i >> 6, k = i & 63; int gr = row0 + r;
        As[r][k] = (gr < N_NODES) ? g_h[gr * 64 + k] : 0.f;
    }
    __syncthreads();

    int c  = t & 127;
    int rb = t >> 7;                // 0..1, 16 rows each
    float acc[16];
    #pragma unroll
    for (int r = 0; r < 16; r++) acc[r] = 0.f;

    #pragma unroll
    for (int k4 = 0; k4 < 16; k4++) {
        float4 w4 = *(const float4*)&Ws[c][k4 * 4];
        #pragma unroll
        for (int r = 0; r < 16; r++) {
            float4 a4 = *(const float4*)&As[rb * 16 + r][k4 * 4];
            acc[r] += w4.x * a4.x + w4.y * a4.y + w4.z * a4.z + w4.w * a4.w;
        }
    }
    float bb = bias[c];
    #pragma unroll
    for (int r = 0; r < 16; r++) {
        int gr = row0 + rb * 16 + r;
        if (gr < N_NODES)
            atomicAdd(&pooled[batch[gr] * DOUT + c], acc[r] + bb);
    }
}

__global__ void finalize(float* __restrict__ out) {
    int idx = blockIdx.x * blockDim.x + threadIdx.x;
    if (idx >= G_GRAPHS * DOUT) return;
    out[idx] /= fmaxf(g_cnt[idx >> 7], 1.f);
}

// ---------------- launch ----------------
extern "C" void kernel_launch(void* const* d_in, const int* in_sizes, int n_in,
                              void* d_out, int out_size) {
    const float* x         = (const float*)d_in[0];
    const int*   ei        = (const int*)  d_in[1];
    const float* eattr     = (const float*)d_in[2];
    const int*   batch     = (const int*)  d_in[3];
    const float* emb_W     = (const float*)d_in[4];
    const float* emb_b     = (const float*)d_in[5];
    const float* Wl        = (const float*)d_in[6];
    const float* bl        = (const float*)d_in[7];
    const float* Wr        = (const float*)d_in[8];
    const float* br        = (const float*)d_in[9];
    const float* We        = (const float*)d_in[10];
    const float* att       = (const float*)d_in[11];
    const float* conv_bias = (const float*)d_in[12];
    const float* gamma     = (const float*)d_in[13];
    const float* beta      = (const float*)d_in[14];
    const float* mean      = (const float*)d_in[15];
    const float* var       = (const float*)d_in[16];
    const float* lin_W     = (const float*)d_in[17];
    const float* lin_b     = (const float*)d_in[18];
    float* out = (float*)d_out;

    const int GEMM_BLOCKS  = (N_NODES + 63) / 64;           // 782
    const int NODE_BLOCKS  = (N_NODES * HID + 255) / 256;   // 12500
    const int EDGE_BLOCKS  = (E_EDGES + 7) / 8;             // 100000 (8 warps/block)

    // embedding + zero accumulators (acc/denom are also re-zeroed by node_update)
    gemm64<<<GEMM_BLOCKS, 256>>>(x, emb_W, emb_b, /*src*/0, /*dst g_h*/0, N_NODES);
    init_acc<<<NODE_BLOCKS, 256>>>();

    for (int l = 0; l < LAYERS; l++) {
        gemm64<<<GEMM_BLOCKS, 256>>>(nullptr, Wl + l * 4096, bl + l * 64, 1, 1, N_NODES); // xl
        gemm64<<<GEMM_BLOCKS, 256>>>(nullptr, Wr + l * 4096, br + l * 64, 1, 2, N_NODES); // xr
        edge_pass<<<EDGE_BLOCKS, 256>>>(ei, eattr, We + l * 1024, att + l * 64);
        node_update<<<NODE_BLOCKS, 256>>>(conv_bias + l * 64, gamma + l * 64, beta + l * 64,
                                          mean + l * 64, var + l * 64);
    }

    init_pool<<<(G_GRAPHS * DOUT + 255) / 256, 256>>>(out);
    count_nodes<<<(N_NODES + 255) / 256, 256>>>(batch);
    lin_pool<<<(N_NODES + 31) / 32, 256>>>(lin_W, lin_b, batch, out);
    finalize<<<(G_GRAPHS * DOUT + 255) / 256, 256>>>(out);
}

// round 3
// speedup vs baseline: 1.5281x; 1.4092x over previous
#include <cuda_runtime.h>
#include <math.h>

#define N_NODES 50000
#define E_EDGES 800000
#define G_GRAPHS 512
#define HID 64
#define DOUT 128
#define LAYERS 3
#define NEG_SLOPE 0.2f
#define BN_EPS 1e-5f

// ---------------- scratch (device globals; no allocation allowed) ----------------
__device__ float g_h  [N_NODES * HID];
__device__ float g_xl [N_NODES * HID];
__device__ float g_xr [N_NODES * HID];
__device__ int   g_hist[N_NODES];
__device__ int   g_off [N_NODES + 1];
__device__ int   g_cursor[N_NODES];
__device__ int   g_srcS[E_EDGES];
__device__ float g_eaS [E_EDGES * 16];
__device__ float g_cnt [G_GRAPHS];

// ---------------- embedding GEMM (also zeroes histogram for CSR build) ----------
// out g_h[n][c] = sum_k x[n][k]*W[c][k] + b[c]
__global__ void gemm_emb(const float* __restrict__ A, const float* __restrict__ W,
                         const float* __restrict__ bias) {
    __shared__ float Ws[64][68];
    __shared__ float As[64][68];
    int t = threadIdx.x;           // 256 threads
    int row0 = blockIdx.x * 64;

    int gid = blockIdx.x * 256 + t;
    if (gid < N_NODES) g_hist[gid] = 0;   // piggyback: zero histogram

    #pragma unroll
    for (int i = t; i < 4096; i += 256) { int c = i >> 6, k = i & 63; Ws[c][k] = W[i]; }
    #pragma unroll
    for (int i = t; i < 4096; i += 256) {
        int r = i >> 6, k = i & 63; int gr = row0 + r;
        As[r][k] = (gr < N_NODES) ? A[gr * 64 + k] : 0.f;
    }
    __syncthreads();

    int c  = t & 63;
    int rb = t >> 6;
    float acc[16];
    #pragma unroll
    for (int r = 0; r < 16; r++) acc[r] = 0.f;

    #pragma unroll
    for (int k4 = 0; k4 < 16; k4++) {
        float4 w4 = *(const float4*)&Ws[c][k4 * 4];
        #pragma unroll
        for (int r = 0; r < 16; r++) {
            float4 a4 = *(const float4*)&As[rb * 16 + r][k4 * 4];
            acc[r] += w4.x * a4.x + w4.y * a4.y + w4.z * a4.z + w4.w * a4.w;
        }
    }
    float bb = bias[c];
    #pragma unroll
    for (int r = 0; r < 16; r++) {
        int gr = row0 + rb * 16 + r;
        if (gr < N_NODES) g_h[gr * 64 + c] = acc[r] + bb;
    }
}

// ---------------- CSR build ----------------
__global__ void hist_count(const int* __restrict__ ei) {
    int e = blockIdx.x * blockDim.x + threadIdx.x;
    if (e < E_EDGES) atomicAdd(&g_hist[ei[E_EDGES + e]], 1);
}

__global__ void scan_hist() {      // single block, 1024 threads
    __shared__ int sp[1024];
    const int CH = 49;             // 1024*49 = 50176 >= 50000
    int t = threadIdx.x;
    int base = t * CH;
    int sum = 0;
    for (int i = 0; i < CH; i++) {
        int idx = base + i;
        if (idx < N_NODES) sum += g_hist[idx];
    }
    sp[t] = sum;
    __syncthreads();
    // inclusive scan over 1024 partials
    for (int off = 1; off < 1024; off <<= 1) {
        int v = (t >= off) ? sp[t - off] : 0;
        __syncthreads();
        sp[t] += v;
        __syncthreads();
    }
    int run = (t == 0) ? 0 : sp[t - 1];
    for (int i = 0; i < CH; i++) {
        int idx = base + i;
        if (idx < N_NODES) {
            g_off[idx] = run;
            g_cursor[idx] = run;
            run += g_hist[idx];
        }
    }
    if (t == 1023) g_off[N_NODES] = sp[1023];
}

__global__ void scatter_edges(const int* __restrict__ ei, const float* __restrict__ eattr) {
    int e = blockIdx.x * blockDim.x + threadIdx.x;
    if (e >= E_EDGES) return;
    int src = ei[e];
    int dst = ei[E_EDGES + e];
    int pos = atomicAdd(&g_cursor[dst], 1);
    g_srcS[pos] = src;
    const float4* s4 = (const float4*)(eattr + (size_t)e * 16);
    float4* d4 = (float4*)(g_eaS + (size_t)pos * 16);
    d4[0] = s4[0]; d4[1] = s4[1]; d4[2] = s4[2]; d4[3] = s4[3];
}

// ---------------- fused xl/xr GEMM (transposed W in smem: conflict-free) --------
__global__ void gemm_xlxr(const float* __restrict__ Wl, const float* __restrict__ bl,
                          const float* __restrict__ Wr, const float* __restrict__ br) {
    __shared__ float sWlT[64][64];   // [k][c]
    __shared__ float sWrT[64][64];
    __shared__ float sA[32][64];
    int t = threadIdx.x;             // 256
    int row0 = blockIdx.x * 32;

    #pragma unroll
    for (int i = t; i < 4096; i += 256) {
        int c = i >> 6, k = i & 63;
        sWlT[k][c] = Wl[i];
        sWrT[k][c] = Wr[i];
    }
    #pragma unroll
    for (int i = t; i < 2048; i += 256) {
        int r = i >> 6, k = i & 63; int gr = row0 + r;
        sA[r][k] = (gr < N_NODES) ? g_h[gr * 64 + k] : 0.f;
    }
    __syncthreads();

    int c  = t & 63;
    int rb = t >> 6;                 // 0..3, rows rb*8 .. rb*8+7
    float accL[8], accR[8];
    #pragma unroll
    for (int r = 0; r < 8; r++) { accL[r] = 0.f; accR[r] = 0.f; }

    #pragma unroll
    for (int k4 = 0; k4 < 16; k4++) {
        float wl_[4], wr_[4];
        #pragma unroll
        for (int q = 0; q < 4; q++) { wl_[q] = sWlT[k4 * 4 + q][c]; wr_[q] = sWrT[k4 * 4 + q][c]; }
        #pragma unroll
        for (int r = 0; r < 8; r++) {
            float4 a = *(const float4*)&sA[rb * 8 + r][k4 * 4];
            accL[r] += wl_[0] * a.x + wl_[1] * a.y + wl_[2] * a.z + wl_[3] * a.w;
            accR[r] += wr_[0] * a.x + wr_[1] * a.y + wr_[2] * a.z + wr_[3] * a.w;
        }
    }
    float bll = bl[c], brr = br[c];
    #pragma unroll
    for (int r = 0; r < 8; r++) {
        int gr = row0 + rb * 8 + r;
        if (gr < N_NODES) {
            g_xl[gr * 64 + c] = accL[r] + bll;
            g_xr[gr * 64 + c] = accR[r] + brr;
        }
    }
}

// ---------------- fused GAT layer: warp per dst node, zero atomics ---------------
__global__ void gat_layer(const float* __restrict__ We, const float* __restrict__ att,
                          const float* __restrict__ cb, const float* __restrict__ gamma,
                          const float* __restrict__ beta, const float* __restrict__ mean,
                          const float* __restrict__ var) {
    int wid = (blockIdx.x * blockDim.x + threadIdx.x) >> 5;
    if (wid >= N_NODES) return;
    int lane = threadIdx.x & 31;
    int c0 = lane * 2;

    // We rows c0, c0+1 into registers (We is [64][16] row-major)
    float w0[16], w1[16];
    const float4* We4 = (const float4*)We;
    #pragma unroll
    for (int q = 0; q < 4; q++) {
        float4 a = __ldg(&We4[c0 * 4 + q]);
        w0[q * 4] = a.x; w0[q * 4 + 1] = a.y; w0[q * 4 + 2] = a.z; w0[q * 4 + 3] = a.w;
        float4 b = __ldg(&We4[(c0 + 1) * 4 + q]);
        w1[q * 4] = b.x; w1[q * 4 + 1] = b.y; w1[q * 4 + 2] = b.z; w1[q * 4 + 3] = b.w;
    }
    float att0 = __ldg(&att[c0]), att1 = __ldg(&att[c0 + 1]);

    float2 vr = *(const float2*)&g_xr[wid * 64 + c0];
    int jb = g_off[wid], je = g_off[wid + 1];

    float acc0 = 0.f, acc1 = 0.f, accd = 0.f;
    for (int j = jb; j < je; j++) {
        int s = __ldg(&g_srcS[j]);
        float2 vl = *(const float2*)&g_xl[s * 64 + c0];
        const float4* ea4 = (const float4*)(g_eaS + (size_t)j * 16);
        float4 a0 = ea4[0], a1 = ea4[1], a2 = ea4[2], a3 = ea4[3];
        float ar[16] = {a0.x, a0.y, a0.z, a0.w, a1.x, a1.y, a1.z, a1.w,
                        a2.x, a2.y, a2.z, a2.w, a3.x, a3.y, a3.z, a3.w};
        float m0 = vl.x + vr.x;
        float m1 = vl.y + vr.y;
        #pragma unroll
        for (int k = 0; k < 16; k++) {
            m0 = fmaf(w0[k], ar[k], m0);
            m1 = fmaf(w1[k], ar[k], m1);
        }
        m0 = fmaxf(m0, NEG_SLOPE * m0);   // leaky relu
        m1 = fmaxf(m1, NEG_SLOPE * m1);
        float p = m0 * att0 + m1 * att1;
        #pragma unroll
        for (int o = 16; o; o >>= 1) p += __shfl_xor_sync(0xffffffffu, p, o);
        float w = __expf(p);              // logits are small; stable without segment-max
        accd += w;
        acc0 = fmaf(w, vl.x, acc0);
        acc1 = fmaf(w, vl.y, acc1);
    }

    float inv = 1.f / (accd + 1e-16f);
    float o0 = acc0 * inv + __ldg(&cb[c0]);
    float o1 = acc1 * inv + __ldg(&cb[c0 + 1]);
    o0 = (o0 - __ldg(&mean[c0]))     * rsqrtf(__ldg(&var[c0])     + BN_EPS) * __ldg(&gamma[c0])     + __ldg(&beta[c0]);
    o1 = (o1 - __ldg(&mean[c0 + 1])) * rsqrtf(__ldg(&var[c0 + 1]) + BN_EPS) * __ldg(&gamma[c0 + 1]) + __ldg(&beta[c0 + 1]);
    o0 = 0.5f * o0 * (1.f + erff(o0 * 0.70710678118654752f));
    o1 = 0.5f * o1 * (1.f + erff(o1 * 0.70710678118654752f));

    float2 h = *(float2*)&g_h[wid * 64 + c0];
    h.x += o0; h.y += o1;
    *(float2*)&g_h[wid * 64 + c0] = h;
}

// ---------------- pooling ----------------
__global__ void init_pool(float* __restrict__ out) {
    int idx = blockIdx.x * blockDim.x + threadIdx.x;
    if (idx < G_GRAPHS * DOUT) out[idx] = 0.f;
    if (idx < G_GRAPHS) g_cnt[idx] = 0.f;
}

__global__ void count_nodes(const int* __restrict__ batch) {
    int n = blockIdx.x * blockDim.x + threadIdx.x;
    if (n < N_NODES) atomicAdd(&g_cnt[batch[n]], 1.f);
}

__global__ void lin_pool(const float* __restrict__ W, const float* __restrict__ bias,
                         const int* __restrict__ batch, float* __restrict__ pooled) {
    __shared__ float Ws[128][68];
    __shared__ float As[32][68];
    int t = threadIdx.x;            // 256
    int row0 = blockIdx.x * 32;

    for (int i = t; i < 128 * 64; i += 256) { int c = i >> 6, k = i & 63; Ws[c][k] = W[i]; }
    for (int i = t; i < 32 * 64; i += 256) {
        int r = i >> 6, k = i & 63; int gr = row0 + r;
        As[r][k] = (gr < N_NODES) ? g_h[gr * 64 + k] : 0.f;
    }
    __syncthreads();

    int c  = t & 127;
    int rb = t >> 7;
    float acc[16];
    #pragma unroll
    for (int r = 0; r < 16; r++) acc[r] = 0.f;

    #pragma unroll
    for (int k4 = 0; k4 < 16; k4++) {
        float4 w4 = *(const float4*)&Ws[c][k4 * 4];
        #pragma unroll
        for (int r = 0; r < 16; r++) {
            float4 a4 = *(const float4*)&As[rb * 16 + r][k4 * 4];
            acc[r] += w4.x * a4.x + w4.y * a4.y + w4.z * a4.z + w4.w * a4.w;
        }
    }
    float bb = bias[c];
    #pragma unroll
    for (int r = 0; r < 16; r++) {
        int gr = row0 + rb * 16 + r;
        if (gr < N_NODES)
            atomicAdd(&pooled[batch[gr] * DOUT + c], acc[r] + bb);
    }
}

__global__ void finalize(float* __restrict__ out) {
    int idx = blockIdx.x * blockDim.x + threadIdx.x;
    if (idx >= G_GRAPHS * DOUT) return;
    out[idx] /= fmaxf(g_cnt[idx >> 7], 1.f);
}

// ---------------- launch ----------------
extern "C" void kernel_launch(void* const* d_in, const int* in_sizes, int n_in,
                              void* d_out, int out_size) {
    const float* x         = (const float*)d_in[0];
    const int*   ei        = (const int*)  d_in[1];
    const float* eattr     = (const float*)d_in[2];
    const int*   batch     = (const int*)  d_in[3];
    const float* emb_W     = (const float*)d_in[4];
    const float* emb_b     = (const float*)d_in[5];
    const float* Wl        = (const float*)d_in[6];
    const float* bl        = (const float*)d_in[7];
    const float* Wr        = (const float*)d_in[8];
    const float* br        = (const float*)d_in[9];
    const float* We        = (const float*)d_in[10];
    const float* att       = (const float*)d_in[11];
    const float* conv_bias = (const float*)d_in[12];
    const float* gamma     = (const float*)d_in[13];
    const float* beta      = (const float*)d_in[14];
    const float* mean      = (const float*)d_in[15];
    const float* var       = (const float*)d_in[16];
    const float* lin_W     = (const float*)d_in[17];
    const float* lin_b     = (const float*)d_in[18];
    float* out = (float*)d_out;

    const int EMB_BLOCKS  = (N_NODES + 63) / 64;            // 782
    const int XLR_BLOCKS  = (N_NODES + 31) / 32;            // 1563
    const int EDGE_BLOCKS = (E_EDGES + 255) / 256;          // 3125
    const int GAT_BLOCKS  = (N_NODES * 32 + 255) / 256;     // 6250

    // 1..4: embedding (+hist zero) and CSR build
    gemm_emb<<<EMB_BLOCKS, 256>>>(x, emb_W, emb_b);
    hist_count<<<EDGE_BLOCKS, 256>>>(ei);
    scan_hist<<<1, 1024>>>();
    scatter_edges<<<EDGE_BLOCKS, 256>>>(ei, eattr);

    for (int l = 0; l < LAYERS; l++) {
        gemm_xlxr<<<XLR_BLOCKS, 256>>>(Wl + l * 4096, bl + l * 64, Wr + l * 4096, br + l * 64);
        gat_layer<<<GAT_BLOCKS, 256>>>(We + l * 1024, att + l * 64, conv_bias + l * 64,
                                       gamma + l * 64, beta + l * 64, mean + l * 64, var + l * 64);
    }

    init_pool<<<(G_GRAPHS * DOUT + 255) / 256, 256>>>(out);
    count_nodes<<<(N_NODES + 255) / 256, 256>>>(batch);
    lin_pool<<<(N_NODES + 31) / 32, 256>>>(lin_W, lin_b, batch, out);
    finalize<<<(G_GRAPHS * DOUT + 255) / 256, 256>>>(out);
}